// round 9
// baseline (speedup 1.0000x reference)
#include <cuda_runtime.h>
#include <cstdint>

// Shapes fixed by the problem: N=8192, D=64.
#define N_ROWS 8192
#define D_DIM  64

#define COLS4          (N_ROWS / 4)       // 2048 float4 per row
#define THREADS        256

// TMA-store geometry: each block owns 4 full rows (128KB contiguous output).
#define ROWS_PER_BLOCK 4
#define OUT_BLOCKS     (N_ROWS / ROWS_PER_BLOCK)   // 2048
#define CHUNK_FLOATS   2048                        // 8KB per bulk store
#define CHUNK4         (CHUNK_FLOATS / 4)          // 512 float4
#define CHUNK_BYTES    (CHUNK_FLOATS * 4)          // 8192
#define CHUNKS_PER_ROW (N_ROWS / CHUNK_FLOATS)     // 4

// Scratch for GEMV results (no cudaMalloc allowed).
__device__ float g_s1[N_ROWS];
__device__ float g_s2[N_ROWS];

// Kernel 1: s1 = Wh @ a[:64], s2 = Wh @ a[64:128].
// One warp per row; each lane owns a float2 (64 elems / 32 lanes).
__global__ void gemv_kernel(const float* __restrict__ Wh,
                            const float* __restrict__ a) {
    const int warps_per_block = blockDim.x >> 5;
    const int row  = blockIdx.x * warps_per_block + (threadIdx.x >> 5);
    const int lane = threadIdx.x & 31;

    const float2 w  = reinterpret_cast<const float2*>(Wh + (size_t)row * D_DIM)[lane];
    const float2 a1 = reinterpret_cast<const float2*>(a)[lane];
    const float2 a2 = reinterpret_cast<const float2*>(a + D_DIM)[lane];

    float s1 = w.x * a1.x + w.y * a1.y;
    float s2 = w.x * a2.x + w.y * a2.y;

    #pragma unroll
    for (int off = 16; off > 0; off >>= 1) {
        s1 += __shfl_xor_sync(0xFFFFFFFFu, s1, off);
        s2 += __shfl_xor_sync(0xFFFFFFFFu, s2, off);
    }
    if (lane == 0) {
        g_s1[row] = s1;
        g_s2[row] = s2;
    }
    cudaTriggerProgrammaticLaunchCompletion();
}

__device__ __forceinline__ float leaky(float e) {
    // e >= 0 ? e : 0.2*e  ==  max(e, 0.2*e) for all e
    return fmaxf(e, 0.2f * e);
}

__device__ __forceinline__ float4 row_vals(float s1, float4 s2) {
    float4 e;
    e.x = leaky(s1 + s2.x);
    e.y = leaky(s1 + s2.y);
    e.z = leaky(s1 + s2.z);
    e.w = leaky(s1 + s2.w);
    return e;
}

// Kernel 2 (TMA-store version): out[i][j] = leaky(s1[i] + s2[j]).
// Each block writes 4 full rows = 128KB contiguous. Compute goes into
// double-buffered 8KB smem chunks; a single elected thread fires
// cp.async.bulk (8KB contiguous descriptor) per chunk. The TMA engine
// emits ordered full-line bursts -> probe DRAM write-burst efficiency
// vs the warp-STG plateau (~6.2 TB/s).
__global__ __launch_bounds__(THREADS) void outer_tma_kernel(float* __restrict__ out) {
    __shared__ float4 s2_sm[COLS4];          // full s2 vector, 32KB
    __shared__ float4 stage[2][CHUNK4];      // 2 x 8KB staging

    const int t    = threadIdx.x;
    const int row0 = blockIdx.x * ROWS_PER_BLOCK;

    // Wait for gemv's stores (PDL).
    cudaGridDependencySynchronize();

    // Stage the full s2 vector once.
    #pragma unroll
    for (int i = 0; i < COLS4 / THREADS; i++)
        s2_sm[t + i * THREADS] = reinterpret_cast<const float4*>(g_s2)[t + i * THREADS];
    __syncthreads();

    const uint32_t stage_addr0 = (uint32_t)__cvta_generic_to_shared(&stage[0][0]);
    const uint32_t stage_addr1 = (uint32_t)__cvta_generic_to_shared(&stage[1][0]);

    int it = 0;
    for (int r = 0; r < ROWS_PER_BLOCK; r++) {
        const float s1 = g_s1[row0 + r];
        float* dst_row = out + (size_t)(row0 + r) * N_ROWS;

        for (int c = 0; c < CHUNKS_PER_ROW; c++, it++) {
            const int buf = it & 1;

            // Recycle the buffer issued two chunks ago.
            if (it >= 2 && t == 0)
                asm volatile("cp.async.bulk.wait_group.read 1;" ::: "memory");
            __syncthreads();

            // Compute 8KB chunk into the staging buffer (coalesced STS.128).
            #pragma unroll
            for (int k = 0; k < CHUNK4 / THREADS; k++) {
                const int idx = t + k * THREADS;
                stage[buf][idx] = row_vals(s1, s2_sm[c * CHUNK4 + idx]);
            }
            __syncthreads();

            // Elected thread fires the bulk store.
            if (t == 0) {
                asm volatile("fence.proxy.async.shared::cta;" ::: "memory");
                asm volatile(
                    "cp.async.bulk.global.shared::cta.bulk_group [%0], [%1], %2;"
                    :: "l"(dst_row + c * CHUNK_FLOATS),
                       "r"(buf ? stage_addr1 : stage_addr0),
                       "r"((unsigned)CHUNK_BYTES)
                    : "memory");
                asm volatile("cp.async.bulk.commit_group;" ::: "memory");
            }
        }
    }

    // Drain all outstanding bulk stores before kernel exit.
    if (t == 0)
        asm volatile("cp.async.bulk.wait_group 0;" ::: "memory");
}

extern "C" void kernel_launch(void* const* d_in, const int* in_sizes, int n_in,
                              void* d_out, int out_size) {
    const float* Wh = (const float*)d_in[0];
    const float* a  = (const float*)d_in[1];
    float* out = (float*)d_out;

    // Kernel 1: 8192 warps -> 8 warps/block, 1024 blocks.
    gemv_kernel<<<N_ROWS / 8, 256>>>(Wh, a);

    // Kernel 2 with PDL: 2048 blocks, 4 full rows each.
    cudaLaunchConfig_t cfg = {};
    cfg.gridDim  = dim3(OUT_BLOCKS);
    cfg.blockDim = dim3(THREADS);
    cfg.dynamicSmemBytes = 0;
    cfg.stream = 0;

    cudaLaunchAttribute attr[1];
    attr[0].id = cudaLaunchAttributeProgrammaticStreamSerialization;
    attr[0].val.programmaticStreamSerializationAllowed = 1;
    cfg.attrs = attr;
    cfg.numAttrs = 1;

    cudaLaunchKernelEx(&cfg, outer_tma_kernel, out);
}

// round 10
// speedup vs baseline: 1.0484x; 1.0484x over previous
#include <cuda_runtime.h>
#include <cstdint>

// Shapes fixed by the problem: N=8192, D=64.
#define N_ROWS 8192
#define D_DIM  64

#define COLS8          (N_ROWS / 8)      // 1024 float8 per row
#define THREADS        256
#define STRIP8         256               // float8s per strip (2048 floats/row per block)
#define STRIPS         (COLS8 / STRIP8)  // 4 strips
#define ROWS_PER_BLOCK 32
#define GRID_Y         (N_ROWS / ROWS_PER_BLOCK)   // 256

// Scratch for GEMV results (no cudaMalloc allowed).
__device__ float g_s1[N_ROWS];
__device__ float g_s2[N_ROWS];

// Kernel 1: s1 = Wh @ a[:64], s2 = Wh @ a[64:128].
// One warp per row; each lane owns a float2 (64 elems / 32 lanes).
__global__ void gemv_kernel(const float* __restrict__ Wh,
                            const float* __restrict__ a) {
    const int warps_per_block = blockDim.x >> 5;
    const int row  = blockIdx.x * warps_per_block + (threadIdx.x >> 5);
    const int lane = threadIdx.x & 31;

    const float2 w  = reinterpret_cast<const float2*>(Wh + (size_t)row * D_DIM)[lane];
    const float2 a1 = reinterpret_cast<const float2*>(a)[lane];
    const float2 a2 = reinterpret_cast<const float2*>(a + D_DIM)[lane];

    float s1 = w.x * a1.x + w.y * a1.y;
    float s2 = w.x * a2.x + w.y * a2.y;

    #pragma unroll
    for (int off = 16; off > 0; off >>= 1) {
        s1 += __shfl_xor_sync(0xFFFFFFFFu, s1, off);
        s2 += __shfl_xor_sync(0xFFFFFFFFu, s2, off);
    }
    if (lane == 0) {
        g_s1[row] = s1;
        g_s2[row] = s2;
    }
    cudaTriggerProgrammaticLaunchCompletion();
}

__device__ __forceinline__ float leaky(float e) {
    // e >= 0 ? e : 0.2*e  ==  max(e, 0.2*e) for all e
    return fmaxf(e, 0.2f * e);
}

// 256-bit streaming store (sm_100+): one instruction writes 32B per lane,
// 1KB contiguous per warp.
__device__ __forceinline__ void st_v8_cs(float* p,
                                         float r0, float r1, float r2, float r3,
                                         float r4, float r5, float r6, float r7) {
    asm volatile(
        "st.global.cs.v8.f32 [%0], {%1, %2, %3, %4, %5, %6, %7, %8};"
        :: "l"(p),
           "f"(r0), "f"(r1), "f"(r2), "f"(r3),
           "f"(r4), "f"(r5), "f"(r6), "f"(r7)
        : "memory");
}

// Kernel 2: out[i][j] = leaky(s1[i] + s2[j]).
// Thread t owns float8 column t: each STG.256 is warp-contiguous (1KB/warp).
// Block strip = 2048 floats/row, 32 rows. s2 chunk lives in 8 registers.
__global__ __launch_bounds__(THREADS) void outer_kernel(float* __restrict__ out) {
    const int col  = (blockIdx.x * STRIP8 + threadIdx.x) * 8;  // first float col
    const int row0 = blockIdx.y * ROWS_PER_BLOCK;
    float* dst = out + (size_t)row0 * N_ROWS + col;

    // Wait for gemv's stores (PDL).
    cudaGridDependencySynchronize();

    const float4 s2a = *reinterpret_cast<const float4*>(g_s2 + col);
    const float4 s2b = *reinterpret_cast<const float4*>(g_s2 + col + 4);

    #pragma unroll 4
    for (int r = 0; r < ROWS_PER_BLOCK; r += 2) {
        float v0 = g_s1[row0 + r + 0];
        float v1 = g_s1[row0 + r + 1];

        st_v8_cs(dst,
                 leaky(v0 + s2a.x), leaky(v0 + s2a.y),
                 leaky(v0 + s2a.z), leaky(v0 + s2a.w),
                 leaky(v0 + s2b.x), leaky(v0 + s2b.y),
                 leaky(v0 + s2b.z), leaky(v0 + s2b.w));
        st_v8_cs(dst + N_ROWS,
                 leaky(v1 + s2a.x), leaky(v1 + s2a.y),
                 leaky(v1 + s2a.z), leaky(v1 + s2a.w),
                 leaky(v1 + s2b.x), leaky(v1 + s2b.y),
                 leaky(v1 + s2b.z), leaky(v1 + s2b.w));
        dst += 2 * (size_t)N_ROWS;
    }
}

extern "C" void kernel_launch(void* const* d_in, const int* in_sizes, int n_in,
                              void* d_out, int out_size) {
    const float* Wh = (const float*)d_in[0];
    const float* a  = (const float*)d_in[1];
    float* out = (float*)d_out;

    // Kernel 1: 8192 warps -> 8 warps/block, 1024 blocks.
    gemv_kernel<<<N_ROWS / 8, 256>>>(Wh, a);

    // Kernel 2 with PDL: 4 strips x 256 row-chunks = 1024 blocks.
    cudaLaunchConfig_t cfg = {};
    cfg.gridDim  = dim3(STRIPS, GRID_Y);
    cfg.blockDim = dim3(THREADS);
    cfg.dynamicSmemBytes = 0;
    cfg.stream = 0;

    cudaLaunchAttribute attr[1];
    attr[0].id = cudaLaunchAttributeProgrammaticStreamSerialization;
    attr[0].val.programmaticStreamSerializationAllowed = 1;
    cfg.attrs = attr;
    cfg.numAttrs = 1;

    cudaLaunchKernelEx(&cfg, outer_kernel, out);
}

// round 11
// speedup vs baseline: 1.1002x; 1.0494x over previous
#include <cuda_runtime.h>

// Shapes fixed by the problem: N=8192, D=64.
#define N_ROWS 8192
#define D_DIM  64

#define COLS4   (N_ROWS / 4)   // 2048 float4 per row
#define THREADS 256

// Scratch for GEMV results (no cudaMalloc allowed).
__device__ float g_s1[N_ROWS];
__device__ float g_s2[N_ROWS];

// Kernel 1: s1 = Wh @ a[:64], s2 = Wh @ a[64:128].
// One warp per row; each lane owns a float2 (64 elems / 32 lanes).
__global__ void gemv_kernel(const float* __restrict__ Wh,
                            const float* __restrict__ a) {
    const int warps_per_block = blockDim.x >> 5;
    const int row  = blockIdx.x * warps_per_block + (threadIdx.x >> 5);
    const int lane = threadIdx.x & 31;

    const float2 w  = reinterpret_cast<const float2*>(Wh + (size_t)row * D_DIM)[lane];
    const float2 a1 = reinterpret_cast<const float2*>(a)[lane];
    const float2 a2 = reinterpret_cast<const float2*>(a + D_DIM)[lane];

    float s1 = w.x * a1.x + w.y * a1.y;
    float s2 = w.x * a2.x + w.y * a2.y;

    #pragma unroll
    for (int off = 16; off > 0; off >>= 1) {
        s1 += __shfl_xor_sync(0xFFFFFFFFu, s1, off);
        s2 += __shfl_xor_sync(0xFFFFFFFFu, s2, off);
    }
    if (lane == 0) {
        g_s1[row] = s1;
        g_s2[row] = s2;
    }
    // Release the dependent outer kernel's blocks early (PDL).
    cudaTriggerProgrammaticLaunchCompletion();
}

__device__ __forceinline__ float leaky(float e) {
    // e >= 0 ? e : 0.2*e  ==  max(e, 0.2*e) for all e
    return fmaxf(e, 0.2f * e);
}

// Kernel 2: out[i][j] = leaky(s1[i] + s2[j]); one thread per float4.
// Exact R2 geometry (best measured: 45.0us): 8 blocks x 8192 rows,
// thread-per-float4, 128-bit evict-first stores. PDL added so block
// ramp-up and address math overlap gemv's drain.
__global__ __launch_bounds__(THREADS) void outer_kernel(float4* __restrict__ out) {
    const int row = blockIdx.y;
    const int c4  = blockIdx.x * THREADS + threadIdx.x;   // 0..2047

    float4* dst = &out[(size_t)row * COLS4 + c4];

    // Wait for gemv's stores to be visible.
    cudaGridDependencySynchronize();

    const float  s1 = g_s1[row];
    const float4 s2 = reinterpret_cast<const float4*>(g_s2)[c4];

    float4 e;
    e.x = leaky(s1 + s2.x);
    e.y = leaky(s1 + s2.y);
    e.z = leaky(s1 + s2.z);
    e.w = leaky(s1 + s2.w);

    __stcs(dst, e);
}

extern "C" void kernel_launch(void* const* d_in, const int* in_sizes, int n_in,
                              void* d_out, int out_size) {
    const float* Wh = (const float*)d_in[0];
    const float* a  = (const float*)d_in[1];
    float4* out = (float4*)d_out;

    // Kernel 1: 8192 warps -> 8 warps/block, 1024 blocks.
    gemv_kernel<<<N_ROWS / 8, 256>>>(Wh, a);

    // Kernel 2 with PDL: 8 x 8192 blocks, one float4 per thread.
    cudaLaunchConfig_t cfg = {};
    cfg.gridDim  = dim3(COLS4 / THREADS, N_ROWS);   // (8, 8192)
    cfg.blockDim = dim3(THREADS);
    cfg.dynamicSmemBytes = 0;
    cfg.stream = 0;

    cudaLaunchAttribute attr[1];
    attr[0].id = cudaLaunchAttributeProgrammaticStreamSerialization;
    attr[0].val.programmaticStreamSerializationAllowed = 1;
    cfg.attrs = attr;
    cfg.numAttrs = 1;

    cudaLaunchKernelEx(&cfg, outer_kernel, out);
}